// round 2
// baseline (speedup 1.0000x reference)
#include <cuda_runtime.h>
#include <cuda_bf16.h>

#define BATCH 2
#define NPTS  65536
#define KNN   16
#define DCH   32

// ---------------------------------------------------------------------------
// Kernel 1: computed half. One thread per (b, n, quad-of-4 k's); writes the
// 32 conv+BN+ReLU channels as float4 (16B) each, coalescing to 512B/warp
// per channel.
// ---------------------------------------------------------------------------
__global__ __launch_bounds__(256, 6) void lse_compute_kernel(
    const float* __restrict__ coords,    // (B, N, 3)
    const int*   __restrict__ idx,       // (B, N, K)
    const float* __restrict__ w,         // (D, 10)
    const float* __restrict__ bias,      // (D,)
    const float* __restrict__ gamma,
    const float* __restrict__ beta,
    const float* __restrict__ mean,
    const float* __restrict__ var,
    float* __restrict__ out)             // (B, 2D, N, K)
{
    // Folded per-channel params:
    // dot(w, [ext, nb, ext-nb, dist]) = (w0:3 + w6:9)·ext + (w3:6 - w6:9)·nb + w9*dist
    __shared__ float4 s_wa[DCH];  // we.x, we.y, we.z, wn.x
    __shared__ float4 s_wb[DCH];  // wn.y, wn.z, wd,   bias'
    int t = threadIdx.x;
    if (t < DCH) {
        float sc = gamma[t] * rsqrtf(var[t] + 1e-5f);
        const float* wr = w + t * 10;
        float w0 = wr[0], w1 = wr[1], w2 = wr[2], w3 = wr[3], w4 = wr[4];
        float w5 = wr[5], w6 = wr[6], w7 = wr[7], w8 = wr[8], w9 = wr[9];
        s_wa[t] = make_float4((w0 + w6) * sc, (w1 + w7) * sc, (w2 + w8) * sc,
                              (w3 - w6) * sc);
        s_wb[t] = make_float4((w4 - w7) * sc, (w5 - w8) * sc, w9 * sc,
                              (bias[t] - mean[t]) * sc + beta[t]);
    }
    __syncthreads();

    int gid = blockIdx.x * blockDim.x + t;       // 0 .. B*N*4 - 1
    int kq  = gid & 3;                           // which quad of k
    int n   = (gid >> 2) & (NPTS - 1);
    int b   = gid >> 18;                         // gid / (4*N)

    const float* cb = coords + (size_t)b * NPTS * 3;
    float cx = cb[(size_t)n * 3 + 0];
    float cy = cb[(size_t)n * 3 + 1];
    float cz = cb[(size_t)n * 3 + 2];

    int4 ii = *reinterpret_cast<const int4*>(
        idx + ((size_t)b * NPTS + (size_t)n) * KNN + kq * 4);

    float nx[4], ny[4], nz[4], dist[4];
#pragma unroll
    for (int j = 0; j < 4; j++) {
        int id = (&ii.x)[j];
        float x = __ldg(cb + (size_t)id * 3 + 0);
        float y = __ldg(cb + (size_t)id * 3 + 1);
        float z = __ldg(cb + (size_t)id * 3 + 2);
        nx[j] = x; ny[j] = y; nz[j] = z;
        float ddx = cx - x, ddy = cy - y, ddz = cz - z;
        dist[j] = sqrtf(ddx * ddx + ddy * ddy + ddz * ddz);
    }

    const size_t cstride = (size_t)NPTS * KNN;   // per-channel stride in out
    size_t out_base = (size_t)b * 2 * DCH * cstride + (size_t)n * KNN
                      + (size_t)kq * 4;

#pragma unroll
    for (int o = 0; o < DCH; o++) {
        float4 wa = s_wa[o];
        float4 wb = s_wb[o];
        float base = wb.w + wa.x * cx + wa.y * cy + wa.z * cz;
        float4 r;
        float* rp = &r.x;
#pragma unroll
        for (int j = 0; j < 4; j++) {
            float v = base + wa.w * nx[j] + wb.x * ny[j] + wb.y * nz[j]
                           + wb.z * dist[j];
            rp[j] = fmaxf(v, 0.0f);
        }
        *reinterpret_cast<float4*>(out + out_base + (size_t)o * cstride) = r;
    }
}

// ---------------------------------------------------------------------------
// Kernel 2: feature-broadcast half. One thread per (b, c, n): load one float,
// write 16 copies = 64 contiguous bytes (4x STG.128). Warp writes 2KB
// contiguous. Tiny register footprint -> full occupancy -> max store BW.
// ---------------------------------------------------------------------------
__global__ __launch_bounds__(256) void lse_feat_kernel(
    const float* __restrict__ features,  // (B, D, N, 1)
    float* __restrict__ out)             // (B, 2D, N, K)
{
    int gid = blockIdx.x * blockDim.x + threadIdx.x;  // over B*DCH*NPTS
    int n = gid & (NPTS - 1);
    int c = (gid >> 16) & (DCH - 1);
    int b = gid >> 21;

    float f = features[((size_t)b * DCH + c) * NPTS + n];
    float4 v = make_float4(f, f, f, f);

    size_t base = ((size_t)b * 2 * DCH + DCH + c) * ((size_t)NPTS * KNN)
                  + (size_t)n * KNN;
    float4* p = reinterpret_cast<float4*>(out + base);
    p[0] = v; p[1] = v; p[2] = v; p[3] = v;
}

extern "C" void kernel_launch(void* const* d_in, const int* in_sizes, int n_in,
                              void* d_out, int out_size) {
    const float* coords   = (const float*)d_in[0];
    const float* features = (const float*)d_in[1];
    const int*   idx      = (const int*)d_in[2];
    const float* w        = (const float*)d_in[3];
    const float* bias     = (const float*)d_in[4];
    const float* gamma    = (const float*)d_in[5];
    const float* beta     = (const float*)d_in[6];
    const float* mean     = (const float*)d_in[7];
    const float* var      = (const float*)d_in[8];
    float* out = (float*)d_out;

    {   // computed half: one thread per (b, n, k-quad)
        const int total   = BATCH * NPTS * 4;
        const int threads = 256;
        lse_compute_kernel<<<total / threads, threads>>>(
            coords, idx, w, bias, gamma, beta, mean, var, out);
    }
    {   // feature half: one thread per (b, c, n)
        const int total   = BATCH * DCH * NPTS;
        const int threads = 256;
        lse_feat_kernel<<<total / threads, threads>>>(features, out);
    }
}

// round 3
// speedup vs baseline: 1.0738x; 1.0738x over previous
#include <cuda_runtime.h>
#include <cuda_bf16.h>

#define BATCH 2
#define NPTS  65536
#define KNN   16
#define DCH   32

// Fused kernel: one thread per (b, n, quad-of-4 k's). Writes all 64 output
// channels (32 computed + 32 feature-broadcast) as float4, interleaved so the
// store stream stays deep and feature loads are hoisted by the unroller.
__global__ __launch_bounds__(256, 6) void lse_kernel(
    const float* __restrict__ coords,    // (B, N, 3)
    const float* __restrict__ features,  // (B, D, N, 1)
    const int*   __restrict__ idx,       // (B, N, K)
    const float* __restrict__ w,         // (D, 10)
    const float* __restrict__ bias,      // (D,)
    const float* __restrict__ gamma,
    const float* __restrict__ beta,
    const float* __restrict__ mean,
    const float* __restrict__ var,
    float* __restrict__ out)             // (B, 2D, N, K)
{
    // Folded per-channel params:
    // dot(w, [ext, nb, ext-nb, dist]) = (w0:3 + w6:9)·ext + (w3:6 - w6:9)·nb + w9*dist
    __shared__ float4 s_wa[DCH];  // we.x, we.y, we.z, wn.x
    __shared__ float4 s_wb[DCH];  // wn.y, wn.z, wd,   bias'
    int t = threadIdx.x;
    if (t < DCH) {
        float sc = gamma[t] * rsqrtf(var[t] + 1e-5f);
        const float* wr = w + t * 10;
        float w0 = wr[0], w1 = wr[1], w2 = wr[2], w3 = wr[3], w4 = wr[4];
        float w5 = wr[5], w6 = wr[6], w7 = wr[7], w8 = wr[8], w9 = wr[9];
        s_wa[t] = make_float4((w0 + w6) * sc, (w1 + w7) * sc, (w2 + w8) * sc,
                              (w3 - w6) * sc);
        s_wb[t] = make_float4((w4 - w7) * sc, (w5 - w8) * sc, w9 * sc,
                              (bias[t] - mean[t]) * sc + beta[t]);
    }
    __syncthreads();

    int gid = blockIdx.x * blockDim.x + t;       // 0 .. B*N*4 - 1
    int kq  = gid & 3;                           // which quad of k
    int n   = (gid >> 2) & (NPTS - 1);
    int b   = gid >> 18;                         // gid / (4*N)

    const float* cb = coords + (size_t)b * NPTS * 3;
    float cx = cb[(size_t)n * 3 + 0];
    float cy = cb[(size_t)n * 3 + 1];
    float cz = cb[(size_t)n * 3 + 2];

    int4 ii = *reinterpret_cast<const int4*>(
        idx + ((size_t)b * NPTS + (size_t)n) * KNN + kq * 4);

    float nx[4], ny[4], nz[4], dist[4];
#pragma unroll
    for (int j = 0; j < 4; j++) {
        int id = (&ii.x)[j];
        float x = __ldg(cb + (size_t)id * 3 + 0);
        float y = __ldg(cb + (size_t)id * 3 + 1);
        float z = __ldg(cb + (size_t)id * 3 + 2);
        nx[j] = x; ny[j] = y; nz[j] = z;
        float ddx = cx - x, ddy = cy - y, ddz = cz - z;
        dist[j] = sqrtf(ddx * ddx + ddy * ddy + ddz * ddz);
    }

    const size_t cstride = (size_t)NPTS * KNN;   // per-channel stride in out
    size_t out_base = (size_t)b * 2 * DCH * cstride + (size_t)n * KNN
                      + (size_t)kq * 4;
    const float* fb = features + (size_t)b * DCH * NPTS + (size_t)n;
    float* outc = out + out_base;                        // computed half base
    float* outf = out + out_base + (size_t)DCH * cstride; // feature half base

#pragma unroll
    for (int o = 0; o < DCH; o++) {
        // feature-broadcast store for channel o (independent stream; load
        // gets hoisted ahead by the unroller)
        float f = __ldg(fb + (size_t)o * NPTS);
        *reinterpret_cast<float4*>(outf + (size_t)o * cstride) =
            make_float4(f, f, f, f);

        // computed store for channel o
        float4 wa = s_wa[o];
        float4 wb = s_wb[o];
        float base = wb.w + wa.x * cx + wa.y * cy + wa.z * cz;
        float4 r;
        float* rp = &r.x;
#pragma unroll
        for (int j = 0; j < 4; j++) {
            float v = base + wa.w * nx[j] + wb.x * ny[j] + wb.y * nz[j]
                           + wb.z * dist[j];
            rp[j] = fmaxf(v, 0.0f);
        }
        *reinterpret_cast<float4*>(outc + (size_t)o * cstride) = r;
    }
}

extern "C" void kernel_launch(void* const* d_in, const int* in_sizes, int n_in,
                              void* d_out, int out_size) {
    const float* coords   = (const float*)d_in[0];
    const float* features = (const float*)d_in[1];
    const int*   idx      = (const int*)d_in[2];
    const float* w        = (const float*)d_in[3];
    const float* bias     = (const float*)d_in[4];
    const float* gamma    = (const float*)d_in[5];
    const float* beta     = (const float*)d_in[6];
    const float* mean     = (const float*)d_in[7];
    const float* var      = (const float*)d_in[8];
    float* out = (float*)d_out;

    const int total   = BATCH * NPTS * 4;   // one thread per (b, n, k-quad)
    const int threads = 256;
    lse_kernel<<<total / threads, threads>>>(coords, features, idx, w, bias,
                                             gamma, beta, mean, var, out);
}

// round 4
// speedup vs baseline: 1.2522x; 1.1661x over previous
#include <cuda_runtime.h>
#include <cuda_bf16.h>

#define BATCH 2
#define NPTS  65536
#define KNN   16
#define DCH   32

// One thread handles (b, n, quad-of-4 k's). All 64 output channels for that
// (n, k-quad) are written as float4 streaming stores (evict-first) — the
// output is write-once and must not churn L2.
__global__ __launch_bounds__(256) void lse_kernel(
    const float* __restrict__ coords,    // (B, N, 3)
    const float* __restrict__ features,  // (B, D, N, 1)
    const int*   __restrict__ idx,       // (B, N, K)
    const float* __restrict__ w,         // (D, 10)
    const float* __restrict__ bias,      // (D,)
    const float* __restrict__ gamma,
    const float* __restrict__ beta,
    const float* __restrict__ mean,
    const float* __restrict__ var,
    float* __restrict__ out)             // (B, 2D, N, K)
{
    // Folded per-channel params:
    // dot(w, [ext, nb, ext-nb, dist]) = (w0:3 + w6:9)·ext + (w3:6 - w6:9)·nb + w9*dist
    __shared__ float4 s_wa[DCH];  // we.x, we.y, we.z, wn.x
    __shared__ float4 s_wb[DCH];  // wn.y, wn.z, wd,   bias'
    int t = threadIdx.x;
    if (t < DCH) {
        float sc = gamma[t] * rsqrtf(var[t] + 1e-5f);
        const float* wr = w + t * 10;
        float w0 = wr[0], w1 = wr[1], w2 = wr[2], w3 = wr[3], w4 = wr[4];
        float w5 = wr[5], w6 = wr[6], w7 = wr[7], w8 = wr[8], w9 = wr[9];
        s_wa[t] = make_float4((w0 + w6) * sc, (w1 + w7) * sc, (w2 + w8) * sc,
                              (w3 - w6) * sc);
        s_wb[t] = make_float4((w4 - w7) * sc, (w5 - w8) * sc, w9 * sc,
                              (bias[t] - mean[t]) * sc + beta[t]);
    }
    __syncthreads();

    int gid = blockIdx.x * blockDim.x + t;       // 0 .. B*N*4 - 1
    int kq  = gid & 3;                           // which quad of k
    int n   = (gid >> 2) & (NPTS - 1);
    int b   = gid >> 18;                         // gid / (4*N)

    const float* cb = coords + (size_t)b * NPTS * 3;
    float cx = cb[(size_t)n * 3 + 0];
    float cy = cb[(size_t)n * 3 + 1];
    float cz = cb[(size_t)n * 3 + 2];

    int4 ii = *reinterpret_cast<const int4*>(
        idx + ((size_t)b * NPTS + (size_t)n) * KNN + kq * 4);

    float nx[4], ny[4], nz[4], dist[4];
#pragma unroll
    for (int j = 0; j < 4; j++) {
        int id = (&ii.x)[j];
        float x = __ldg(cb + (size_t)id * 3 + 0);
        float y = __ldg(cb + (size_t)id * 3 + 1);
        float z = __ldg(cb + (size_t)id * 3 + 2);
        nx[j] = x; ny[j] = y; nz[j] = z;
        float ddx = cx - x, ddy = cy - y, ddz = cz - z;
        dist[j] = sqrtf(ddx * ddx + ddy * ddy + ddz * ddz);
    }

    const size_t cstride = (size_t)NPTS * KNN;   // per-channel stride in out
    size_t out_base = (size_t)b * 2 * DCH * cstride + (size_t)n * KNN
                      + (size_t)kq * 4;

    // Computed half: y = relu(conv+BN)
#pragma unroll
    for (int o = 0; o < DCH; o++) {
        float4 wa = s_wa[o];
        float4 wb = s_wb[o];
        float base = wb.w + wa.x * cx + wa.y * cy + wa.z * cz;
        float4 r;
        float* rp = &r.x;
#pragma unroll
        for (int j = 0; j < 4; j++) {
            float v = base + wa.w * nx[j] + wb.x * ny[j] + wb.y * nz[j]
                           + wb.z * dist[j];
            rp[j] = fmaxf(v, 0.0f);
        }
        __stcs(reinterpret_cast<float4*>(out + out_base + (size_t)o * cstride),
               r);
    }

    // Broadcast half: features replicated across K
    const float* fb = features + (size_t)b * DCH * NPTS + (size_t)n;
    size_t fout = out_base + (size_t)DCH * cstride;
#pragma unroll
    for (int c = 0; c < DCH; c++) {
        float f = __ldg(fb + (size_t)c * NPTS);
        __stcs(reinterpret_cast<float4*>(out + fout + (size_t)c * cstride),
               make_float4(f, f, f, f));
    }
}

extern "C" void kernel_launch(void* const* d_in, const int* in_sizes, int n_in,
                              void* d_out, int out_size) {
    const float* coords   = (const float*)d_in[0];
    const float* features = (const float*)d_in[1];
    const int*   idx      = (const int*)d_in[2];
    const float* w        = (const float*)d_in[3];
    const float* bias     = (const float*)d_in[4];
    const float* gamma    = (const float*)d_in[5];
    const float* beta     = (const float*)d_in[6];
    const float* mean     = (const float*)d_in[7];
    const float* var      = (const float*)d_in[8];
    float* out = (float*)d_out;

    const int total   = BATCH * NPTS * 4;   // one thread per (b, n, k-quad)
    const int threads = 256;
    const int blocks  = total / threads;    // 2048
    lse_kernel<<<blocks, threads>>>(coords, features, idx, w, bias,
                                    gamma, beta, mean, var, out);
}